// round 16
// baseline (speedup 1.0000x reference)
#include <cuda_runtime.h>

// SSIM loss, single fused kernel, f32x2 packed math, 2-row LDG prefetch,
// SOFTWARE-PIPELINED vertical pass: iteration i loads row i from smem, then
// runs the vertical scatter + consume of row i-1 while those loads are in
// flight, then does row i's horizontal math. LDS latency hides under ~80cyc
// of register math instead of being exposed every row.
// pred/target: [16,3,512,512] fp32 -> 48 planes of 512x512.
// Grid: 1536 CTAs x 128 threads (4 warps) = 48 planes x 16 strips x 2 halves.
// Warp = 32-col strip x 64 output rows (74 input rows incl. halo).
// Fields packed as a=p+t, b=p-t:
//   accm = (conv(a), conv(b)), accs = (conv(a^2), conv(b^2))
// Ring: slot s first written by row j==s (mod 11) via k=0 MUL (no init).
// All register-array indices compile-time. Last CTA reduces, writes scalar.

static __device__ double g_partials[1536];
static __device__ unsigned int g_count;   // zero-init; reset by last CTA

__device__ __forceinline__ unsigned long long pk2(float lo, float hi) {
    unsigned long long r;
    asm("mov.b64 %0, {%1, %2};" : "=l"(r) : "f"(lo), "f"(hi));
    return r;
}
__device__ __forceinline__ void up2(unsigned long long v, float& lo, float& hi) {
    asm("mov.b64 {%0, %1}, %2;" : "=f"(lo), "=f"(hi) : "l"(v));
}
__device__ __forceinline__ unsigned long long ffma2(unsigned long long a,
                                                    unsigned long long b,
                                                    unsigned long long c) {
    unsigned long long d;
    asm("fma.rn.f32x2 %0, %1, %2, %3;" : "=l"(d) : "l"(a), "l"(b), "l"(c));
    return d;
}
__device__ __forceinline__ unsigned long long fmul2(unsigned long long a,
                                                    unsigned long long b) {
    unsigned long long d;
    asm("mul.rn.f32x2 %0, %1, %2;" : "=l"(d) : "l"(a), "l"(b));
    return d;
}
__device__ __forceinline__ unsigned long long fadd2(unsigned long long a,
                                                    unsigned long long b) {
    unsigned long long d;
    asm("add.rn.f32x2 %0, %1, %2;" : "=l"(d) : "l"(a), "l"(b));
    return d;
}

// Weight by tap index with symmetry (compile-time select of 6 regs).
#define WT(K) (Wp[(K) < 6 ? (K) : 10 - (K)])

// Global loads for input row YY into prefetch regs (clamped address, zeroed
// out-of-range -> matches zero padding). SLOT compile-time at every site.
#define PREFETCH(SLOT, YY) do {                                              \
    const int yc = (YY) < 0 ? 0 : ((YY) > 511 ? 511 : (YY));                 \
    const bool rv = ((YY) >= 0) && ((YY) <= 511);                            \
    const float* __restrict__ Prow = P + yc * 512;                           \
    const float* __restrict__ Trow = T + yc * 512;                           \
    if (rv && v0) { pf_p0[SLOT] = Prow[c0c]; pf_t0[SLOT] = Trow[c0c]; }      \
    else          { pf_p0[SLOT] = 0.0f;      pf_t0[SLOT] = 0.0f;      }      \
    if (lane < 10) {                                                         \
        if (rv && v1) { pf_p1[SLOT] = Prow[c1c]; pf_t1[SLOT] = Trow[c1c]; }  \
        else          { pf_p1[SLOT] = 0.0f;      pf_t1[SLOT] = 0.0f;      }  \
    }                                                                        \
} while (0)

// Store prefetched row SLOT into smem buffer SLOT: (a,b) only.
#define STAGE(SLOT) do {                                                     \
    const float a0 = pf_p0[SLOT] + pf_t0[SLOT];                              \
    const float b0 = pf_p0[SLOT] - pf_t0[SLOT];                              \
    abw[(SLOT) * 48 + lane] = pk2(a0, b0);                                   \
    if (lane < 10) {                                                         \
        const float a1 = pf_p1[SLOT] + pf_t1[SLOT];                          \
        const float b1 = pf_p1[SLOT] - pf_t1[SLOT];                          \
        abw[(SLOT) * 48 + 32 + lane] = pk2(a1, b1);                          \
    }                                                                        \
} while (0)

// Issue the 11 window loads for the current row into tld[] (results used
// only after VPASS/CONSUME -> latency hidden by register math).
#define HLOAD(BUF) do {                                                      \
    const unsigned long long* __restrict__ rm = abw + (BUF) * 48 + lane;     \
    _Pragma("unroll")                                                        \
    for (int d = 0; d < 11; ++d) tld[d] = rm[d];                             \
} while (0)

// Horizontal 11-tap math from tld[]; squares formed on the fly.
#define HMATH() do {                                                         \
    unsigned long long hm0 = 0ull, hm1 = 0ull, hs0 = 0ull, hs1 = 0ull;       \
    _Pragma("unroll")                                                        \
    for (int d = 0; d < 10; d += 2) {                                        \
        const unsigned long long w0 = fmul2(tld[d],     WT(d));              \
        const unsigned long long w1 = fmul2(tld[d + 1], WT(d + 1));          \
        hm0 = ffma2(tld[d],     WT(d),     hm0);                             \
        hm1 = ffma2(tld[d + 1], WT(d + 1), hm1);                             \
        hs0 = ffma2(w0, tld[d],     hs0);                                    \
        hs1 = ffma2(w1, tld[d + 1], hs1);                                    \
    }                                                                        \
    {                                                                        \
        const unsigned long long w = fmul2(tld[10], WT(10));                 \
        hm0 = ffma2(tld[10], WT(10), hm0);                                   \
        hs0 = ffma2(w, tld[10], hs0);                                        \
    }                                                                        \
    hm = fadd2(hm0, hm1);                                                    \
    hs = fadd2(hs0, hs1);                                                    \
} while (0)

// Vertical scatter, prologue row J (taps k = 0..J). k=0 MUL opens slot J.
#define VPASS_PRO(J) do {                                                    \
    accm[(J)] = fmul2(hm, WT(0));                                            \
    accs[(J)] = fmul2(hs, WT(0));                                            \
    _Pragma("unroll")                                                        \
    for (int k = 1; k <= (J); ++k) {                                         \
        const int s = ((J) - k + 22) % 11;                                   \
        accm[s] = ffma2(hm, WT(k), accm[s]);                                 \
        accs[s] = ffma2(hs, WT(k), accs[s]);                                 \
    }                                                                        \
} while (0)

// Vertical scatter, steady row with UM = j mod 11 (compile-time). k=0 tap
// re-opens the slot consumed previously (MUL, no reset).
#define VPASS_ST(UM) do {                                                    \
    accm[(UM)] = fmul2(hm, WT(0));                                           \
    accs[(UM)] = fmul2(hs, WT(0));                                           \
    _Pragma("unroll")                                                        \
    for (int k = 1; k <= 10; ++k) {                                          \
        const int s = ((UM) - k + 22) % 11;                                  \
        accm[s] = ffma2(hm, WT(k), accm[s]);                                 \
        accs[s] = ffma2(hs, WT(k), accs[s]);                                 \
    }                                                                        \
} while (0)

// Consume a completed output row from ring slot S (no reset).
#define CONSUME(S) do {                                                      \
    float Ma, Mb, Sa, Sb;                                                    \
    up2(accm[(S)], Ma, Mb);                                                  \
    up2(accs[(S)], Sa, Sb);                                                  \
    const float A2 = Ma * Ma, B2 = Mb * Mb;                                  \
    const float dd = 0.5f * (A2 - B2);   /* mu1*mu2         */               \
    const float pq = 0.5f * (A2 + B2);   /* mu1^2 + mu2^2   */               \
    const float q1 = 0.5f * (Sa - Sb);   /* 2*E[pt]         */               \
    const float q2 = 0.5f * (Sa + Sb);   /* E[p^2]+E[t^2]   */               \
    const float num = (dd + C1f) * (q1 - dd + C2f);                          \
    const float den = (pq + C1f) * (q2 - pq + C2f);                          \
    lsum += __fdividef(num, den);                                            \
} while (0)

// Pipelined steady step, iteration I (>= 12): stage+load row I, scatter row
// I-1 (UM1 = (I-1) mod 11), consume output row I-11 (slot I mod 11), then
// horizontal math for row I. BUF/UM1/CS compile-time at every site.
#define ROWSTEP(BUF, UM1, CS, I) do {                                        \
    STAGE(BUF);                                                              \
    PREFETCH(BUF, y0 - 3 + (I));   /* row (I)+2 into freed slot */           \
    __syncwarp();                                                            \
    HLOAD(BUF);                                                              \
    VPASS_ST(UM1);                                                           \
    CONSUME(CS);                                                             \
    HMATH();                                                                 \
} while (0)

__global__ __launch_bounds__(128, 4) void ssim_main_kernel(
    const float* __restrict__ pred, const float* __restrict__ target,
    float* __restrict__ out)
{
    constexpr float Wc[6] = {
        0.00102838f, 0.00759876f, 0.03600077f, 0.10936070f, 0.21300553f,
        0.26601212f
    };
    constexpr float C1f = 0.0001f;   // 0.01^2
    constexpr float C2f = 0.0009f;   // 0.03^2

    const int lane  = threadIdx.x & 31;
    const int warp  = threadIdx.x >> 5;
    const int plane = blockIdx.x >> 5;               // 0..47
    const int x0    = ((blockIdx.x >> 1) & 15) << 5; // column tile * 32
    const int half  = blockIdx.x & 1;                // row half (0/1)

    const float* __restrict__ P = pred   + (size_t)plane * (512 * 512);
    const float* __restrict__ T = target + (size_t)plane * (512 * 512);

    const int y0 = half * 256 + (warp << 6);  // first output row (64 rows)
    const int c0 = x0 - 5 + lane;    // staged cols [x0-5, x0+37)
    const int c1 = x0 + 27 + lane;   // extra 10 cols (lanes 0..9)
    const bool v0 = (c0 >= 0) && (c0 < 512);
    const bool v1 = (c1 < 512);
    const int c0c = v0 ? c0 : 0;
    const int c1c = v1 ? c1 : 0;

    __shared__ unsigned long long ab[4][2 * 48];
    unsigned long long* abw = ab[warp];

    unsigned long long Wp[6];
#pragma unroll
    for (int i = 0; i < 6; ++i) Wp[i] = pk2(Wc[i], Wc[i]);

    unsigned long long accm[11], accs[11];   // no init: k0-MUL opens slots
    unsigned long long tld[11];              // pipelined window loads

    float pf_p0[2], pf_t0[2], pf_p1[2], pf_t1[2];
    unsigned long long hm, hs;
    float lsum = 0.0f;

    // Prime prefetch: rows i=0,1 (input rows y0-5, y0-4).
    PREFETCH(0, y0 - 5);
    PREFETCH(1, y0 - 4);

    // ---- Prologue i = 0: stage/load row 0, horizontal math only ----
    STAGE(0);
    PREFETCH(0, y0 - 3);            // row 2
    __syncwarp();
    HLOAD(0);
    HMATH();                         // hm/hs for row 0

    // ---- Prologue i = 1..11: scatter row i-1 (taps k <= i-1) ----
#pragma unroll
    for (int i = 1; i <= 11; ++i) {
        STAGE(i & 1);
        PREFETCH(i & 1, y0 - 3 + i); // row i+2
        __syncwarp();
        HLOAD(i & 1);
        VPASS_PRO(i - 1);
        if (i == 11) CONSUME(0);     // output row 0 (after row 10 scatter)
        HMATH();                     // hm/hs for row i
    }

    // ---- Steady i = 12..55 in two 22-iter blocks ----
    // Block bases 12, 34: (base-1) % 11 == 0 and base even, so for i=base+v:
    //   i & 1        = v & 1        (compile-time)
    //   (i-1) % 11   = v % 11       (compile-time)
    //   i % 11       = (v+1) % 11   (compile-time)
    for (int base = 12; base <= 34; base += 22) {
#pragma unroll
        for (int v = 0; v < 22; ++v) {
            ROWSTEP(v & 1, v % 11, (v + 1) % 11, base + v);
        }
    }

    // ---- Steady tail i = 56..73 (55 % 11 == 0, 56 even: same folding) ----
#pragma unroll
    for (int i = 56; i <= 73; ++i) {
        ROWSTEP(i & 1, (i - 56) % 11, (i - 55) % 11, i);
    }

    // ---- Epilogue: scatter row 73, consume output row 63 ----
    VPASS_ST(73 % 11);               // 73 % 11 == 7
    CONSUME(8);                      // (63) % 11 == 8

    // ---- Reduce: warp shfl -> CTA smem -> per-CTA partial ----
#pragma unroll
    for (int off = 16; off > 0; off >>= 1)
        lsum += __shfl_xor_sync(0xffffffffu, lsum, off);

    __shared__ float wsum[4];
    if (lane == 0) wsum[warp] = lsum;
    __syncthreads();

    if (threadIdx.x == 0) {
        g_partials[blockIdx.x] =
            (double)wsum[0] + (double)wsum[1] + (double)wsum[2] + (double)wsum[3];
        __threadfence();
        const unsigned int prev = atomicAdd(&g_count, 1u);
        wsum[0] = (prev == 1535u) ? 1.0f : 0.0f;
    }
    __syncthreads();

    // Last CTA reduces all partials and writes the scalar output.
    if (wsum[0] != 0.0f) {
        __threadfence();
        double s = 0.0;
        for (int i = threadIdx.x; i < 1536; i += 128) s += g_partials[i];
        __shared__ double sm[128];
        sm[threadIdx.x] = s;
        __syncthreads();
        for (int off = 64; off > 0; off >>= 1) {
            if (threadIdx.x < off) sm[threadIdx.x] += sm[threadIdx.x + off];
            __syncthreads();
        }
        if (threadIdx.x == 0) {
            out[0] = (float)(1.0 - sm[0] * (1.0 / 12582912.0));
            g_count = 0u;   // reset for next graph replay
        }
    }
}

extern "C" void kernel_launch(void* const* d_in, const int* in_sizes, int n_in,
                              void* d_out, int out_size) {
    const float* pred   = (const float*)d_in[0];
    const float* target = (const float*)d_in[1];
    float* out = (float*)d_out;
    (void)in_sizes; (void)n_in; (void)out_size;

    ssim_main_kernel<<<1536, 128>>>(pred, target, out);
}